// round 14
// baseline (speedup 1.0000x reference)
#include <cuda_runtime.h>
#include <cuda_fp16.h>

#define NN   100000
#define NE   3200000
#define FIN  256
#define HC   64      // H1*C1
#define NH   8
#define NCL  41
#define H2S  64      // h2h row stride in halves (128B aligned rows)

// ---------------- scratch (static device globals; no runtime alloc) ----------
__device__ __align__(256) __half Wcg[FIN * 80];    // combined W1 | W1*a_src | W1*a_dst (fp16)
__device__ __align__(256) __half h1h[NN * HC];     // fp16 gemm1 out for agg1 gathers
__device__ __align__(256) __half h1e[NN * HC];     // fp16 ELU output (agg1 -> gemm2)
__device__ __align__(256) float  s1g[NN * NH];
__device__ __align__(256) float  d1g[NN * NH];
__device__ __align__(256) __half h2h[NN * H2S];    // fp16 layer2 features (ch 42..63 stay 0)
__device__ __align__(256) float  s2g[NN];
__device__ __align__(256) float  d2g[NN];
__device__ __align__(256) int    cntg[NN];
__device__ __align__(256) int    offg[NN + 1];
__device__ __align__(256) int    rankg[NE];
__device__ __align__(256) int    csrg[NE];
__device__ __align__(256) int    bsumg[128];

__device__ __forceinline__ float lrelu(float x) { return fmaxf(x, 0.2f * x); }

// ---------------- prep: build combined fp16 weight matrix --------------------
__global__ void prep_kernel(const float* __restrict__ W1, const float* __restrict__ as1,
                            const float* __restrict__ ad1) {
    int k = blockIdx.x * blockDim.x + threadIdx.x;
    if (k >= FIN) return;
    const float* row = W1 + k * 64;
    __half* out = Wcg + k * 80;
#pragma unroll
    for (int c = 0; c < 64; c++) out[c] = __float2half(row[c]);
#pragma unroll
    for (int h = 0; h < 8; h++) {
        float s = 0.f, d = 0.f;
#pragma unroll
        for (int c = 0; c < 8; c++) {
            float v = row[h * 8 + c];
            s += v * __ldg(as1 + h * 8 + c);
            d += v * __ldg(ad1 + h * 8 + c);
        }
        out[64 + h] = __float2half(s);
        out[72 + h] = __float2half(d);
    }
}

// ---------------- GEMM1 (tensor cores): [h1h | s1 | d1] = x @ Wc --------------
__device__ __forceinline__ void ldsm4(unsigned& r0, unsigned& r1, unsigned& r2, unsigned& r3,
                                      unsigned addr) {
    asm volatile("ldmatrix.sync.aligned.m8n8.x4.shared.b16 {%0,%1,%2,%3},[%4];"
                 : "=r"(r0), "=r"(r1), "=r"(r2), "=r"(r3) : "r"(addr));
}
__device__ __forceinline__ void ldsm4t(unsigned& r0, unsigned& r1, unsigned& r2, unsigned& r3,
                                       unsigned addr) {
    asm volatile("ldmatrix.sync.aligned.m8n8.x4.trans.shared.b16 {%0,%1,%2,%3},[%4];"
                 : "=r"(r0), "=r"(r1), "=r"(r2), "=r"(r3) : "r"(addr));
}
__device__ __forceinline__ void mma16816(float* c, unsigned a0, unsigned a1, unsigned a2,
                                         unsigned a3, unsigned b0, unsigned b1) {
    asm volatile("mma.sync.aligned.m16n8k16.row.col.f32.f16.f16.f32 "
                 "{%0,%1,%2,%3},{%4,%5,%6,%7},{%8,%9},{%0,%1,%2,%3};"
                 : "+f"(c[0]), "+f"(c[1]), "+f"(c[2]), "+f"(c[3])
                 : "r"(a0), "r"(a1), "r"(a2), "r"(a3), "r"(b0), "r"(b1));
}

__global__ __launch_bounds__(256) void gemm1_tc(const float* __restrict__ x) {
    __shared__ __align__(16) __half As[128 * 72];
    __shared__ __align__(16) __half Bs[128 * 88];
    int t = threadIdx.x, w = t >> 5, lane = t & 31;
    int m0 = blockIdx.x * 128;

    float acc[10][4];
#pragma unroll
    for (int i = 0; i < 10; i++)
#pragma unroll
        for (int j = 0; j < 4; j++) acc[i][j] = 0.f;

    int arow = t >> 1;
    int ac32 = (t & 1) << 5;
    int gr = m0 + arow; if (gr >= NN) gr = NN - 1;
    const float* xrow = x + (long long)gr * FIN;

    unsigned aBase = (unsigned)__cvta_generic_to_shared(
        &As[((w << 4) + (lane & 15)) * 72 + ((lane >> 4) << 3)]);
    unsigned bRowOff = ((lane & 15) * 88 + ((lane >> 4) << 3)) * 2;

    for (int kb = 0; kb < 2; kb++) {
        __syncthreads();
        for (int idx = t; idx < 128 * 10; idx += 256) {
            int krow = idx / 10, seg = idx % 10;
            *(uint4*)&Bs[krow * 88 + seg * 8] =
                *(const uint4*)&Wcg[(kb * 128 + krow) * 80 + seg * 8];
        }
        for (int c = 0; c < 2; c++) {
            __syncthreads();
            int kc = kb * 128 + c * 64 + ac32;
            uint4 pk[4];
#pragma unroll
            for (int q = 0; q < 4; q++) {
                float4 v0 = __ldg((const float4*)(xrow + kc + q * 8));
                float4 v1 = __ldg((const float4*)(xrow + kc + q * 8 + 4));
                __half2 p0 = __floats2half2_rn(v0.x, v0.y);
                __half2 p1 = __floats2half2_rn(v0.z, v0.w);
                __half2 p2 = __floats2half2_rn(v1.x, v1.y);
                __half2 p3 = __floats2half2_rn(v1.z, v1.w);
                pk[q] = make_uint4(*(unsigned*)&p0, *(unsigned*)&p1,
                                   *(unsigned*)&p2, *(unsigned*)&p3);
            }
#pragma unroll
            for (int q = 0; q < 4; q++)
                *(uint4*)&As[arow * 72 + ac32 + q * 8] = pk[q];
            __syncthreads();
#pragma unroll
            for (int ks = 0; ks < 4; ks++) {
                unsigned a0, a1, a2, a3;
                ldsm4(a0, a1, a2, a3, aBase + ks * 32);
                unsigned bAddr = (unsigned)__cvta_generic_to_shared(
                                     &Bs[(c * 64 + ks * 16) * 88]) + bRowOff;
#pragma unroll
                for (int bt = 0; bt < 5; bt++) {
                    unsigned b0, b1, b2, b3;
                    ldsm4t(b0, b1, b2, b3, bAddr + bt * 32);
                    mma16816(acc[bt * 2],     a0, a1, a2, a3, b0, b1);
                    mma16816(acc[bt * 2 + 1], a0, a1, a2, a3, b2, b3);
                }
            }
        }
    }

    int r0 = m0 + (w << 4) + (lane >> 2);
    int r1 = r0 + 8;
    int cq = (lane & 3) << 1;
#pragma unroll
    for (int nt = 0; nt < 8; nt++) {
        int col = nt * 8 + cq;
        if (r0 < NN) *(__half2*)(h1h + r0 * 64 + col) = __floats2half2_rn(acc[nt][0], acc[nt][1]);
        if (r1 < NN) *(__half2*)(h1h + r1 * 64 + col) = __floats2half2_rn(acc[nt][2], acc[nt][3]);
    }
    if (r0 < NN) {
        s1g[r0 * 8 + cq] = acc[8][0]; s1g[r0 * 8 + cq + 1] = acc[8][1];
        d1g[r0 * 8 + cq] = acc[9][0]; d1g[r0 * 8 + cq + 1] = acc[9][1];
    }
    if (r1 < NN) {
        s1g[r1 * 8 + cq] = acc[8][2]; s1g[r1 * 8 + cq + 1] = acc[8][3];
        d1g[r1 * 8 + cq] = acc[9][2]; d1g[r1 * 8 + cq + 1] = acc[9][3];
    }
}

// ---------------- CSR build ---------------------------------------------------
__global__ void hist_kernel(const int* __restrict__ ei) {
    int e4 = blockIdx.x * blockDim.x + threadIdx.x;
    if (e4 * 4 >= NE) return;
    int4 d = __ldg((const int4*)(ei + NE) + e4);
    int4 r;
    r.x = atomicAdd(cntg + d.x, 1);
    r.y = atomicAdd(cntg + d.y, 1);
    r.z = atomicAdd(cntg + d.z, 1);
    r.w = atomicAdd(cntg + d.w, 1);
    ((int4*)rankg)[e4] = r;
}

__global__ void scan1_kernel() {
    __shared__ int wsum[32];
    int t = threadIdx.x, lane = t & 31, wd = t >> 5;
    int i = blockIdx.x * 1024 + t;
    int v = (i < NN) ? cntg[i] : 0;
    int x = v;
#pragma unroll
    for (int o = 1; o < 32; o <<= 1) {
        int y = __shfl_up_sync(0xffffffffu, x, o);
        if (lane >= o) x += y;
    }
    if (lane == 31) wsum[wd] = x;
    __syncthreads();
    if (wd == 0) {
        int y = wsum[lane];
#pragma unroll
        for (int o = 1; o < 32; o <<= 1) {
            int z = __shfl_up_sync(0xffffffffu, y, o);
            if (lane >= o) y += z;
        }
        wsum[lane] = y;
    }
    __syncthreads();
    int excl = x - v + (wd ? wsum[wd - 1] : 0);
    if (i < NN) offg[i] = excl;
    if (t == 1023) bsumg[blockIdx.x] = excl + v;
}

// fused scan2+scan3
__global__ void scanF_kernel() {
    __shared__ int add_s;
    int t = threadIdx.x, bid = blockIdx.x;
    if (t == 0) {
        int add = 0;
        for (int k = 0; k < bid; k++) add += bsumg[k];
        add_s = add;
        if (bid == 97) {
            int tot = add;
            for (int k = bid; k < 98; k++) tot += bsumg[k];
            offg[NN] = tot;
        }
    }
    __syncthreads();
    int i = bid * 1024 + t;
    if (i < NN) offg[i] += add_s;
}

__global__ void scatter_kernel(const int* __restrict__ ei) {
    int e4 = blockIdx.x * blockDim.x + threadIdx.x;
    if (e4 * 4 >= NE) return;
    int4 s = __ldg((const int4*)ei + e4);
    int4 d = __ldg((const int4*)(ei + NE) + e4);
    int4 r = ((const int4*)rankg)[e4];
    csrg[__ldg(offg + d.x) + r.x] = s.x;
    csrg[__ldg(offg + d.y) + r.y] = s.y;
    csrg[__ldg(offg + d.z) + r.z] = s.z;
    csrg[__ldg(offg + d.w) + r.w] = s.w;
}

// ---------------- agg1: warp per dst, MLP-16 batched gathers ------------------
__global__ __launch_bounds__(256, 4) void agg1_kernel(const float* __restrict__ b1) {
    int w = blockIdx.x * 8 + (threadIdx.x >> 5);
    if (w >= NN) return;
    int l = threadIdx.x & 31;
    int dst = w;
    int hw = l & 7, q = l >> 3;
    float dl = __ldg(d1g + dst * 8 + hw);

    float s8 = __ldg(s1g + dst * 8 + hw);
    float w8 = __expf(lrelu(s8 + dl));
    float ww = __shfl_sync(0xffffffffu, w8, l >> 2);
    unsigned hv = __ldg((const unsigned*)h1h + dst * 32 + l);
    float2 f = __half22float2(*(__half2*)&hv);
    float a0 = ww * f.x, a1 = ww * f.y, z = ww;

    int beg = __ldg(offg + dst), end = __ldg(offg + dst + 1);
    for (int k0 = beg; k0 < end; k0 += 32) {
        int n = end - k0; if (n > 32) n = 32;
        int srcl = __ldg(csrg + k0 + (l < n ? l : n - 1));

        // weight phase: branch-free, 8 groups of 4 edges (tail groups duplicate)
        float wreg[8];
#pragma unroll
        for (int g = 0; g < 8; g++) {
            int e = g * 4 + q; if (e >= n) e = n - 1;
            int sw_ = __shfl_sync(0xffffffffu, srcl, e);
            wreg[g] = __expf(lrelu(__ldg(s1g + sw_ * 8 + hw) + dl));
        }

        // feature phase: groups of 16 edges; 16 independent LDGs in flight
#pragma unroll
        for (int gg = 0; gg < 2; gg++) {
            if (gg * 16 >= n) break;   // warp-uniform
            unsigned hb[16];
#pragma unroll
            for (int u = 0; u < 16; u++) {
                int i = gg * 16 + u; if (i >= n) i = n - 1;
                int src = __shfl_sync(0xffffffffu, srcl, i);
                hb[u] = __ldg((const unsigned*)h1h + src * 32 + l);
            }
#pragma unroll
            for (int u = 0; u < 16; u++) {
                int i = gg * 16 + u;
                float we = __shfl_sync(0xffffffffu, wreg[i >> 2],
                                       ((u & 3) << 3) + (l >> 2));
                if (i >= n) we = 0.f;   // warp-uniform tail mask
                float2 g2 = __half22float2(*(__half2*)&hb[u]);
                a0 += we * g2.x; a1 += we * g2.y; z += we;
            }
        }
    }
    float inv = 1.0f / (z + 1e-16f);
    float v0 = a0 * inv + __ldg(b1 + 2 * l);
    float v1 = a1 * inv + __ldg(b1 + 2 * l + 1);
    v0 = v0 > 0.f ? v0 : expm1f(v0);
    v1 = v1 > 0.f ? v1 : expm1f(v1);
    ((__half2*)(h1e + dst * 64))[l] = __floats2half2_rn(v0, v1);
}

// ---------------- gemm2: 4 nodes per warp, smem-staged h, W2 LDS shared ------
__global__ void gemm2_kernel(const float* __restrict__ W2, const float* __restrict__ a_s,
                             const float* __restrict__ a_d) {
    __shared__ float  Ws[64 * 44];
    __shared__ float  as_s[44], ad_s[44];
    __shared__ float2 hs[8][4][32];
    int t = threadIdx.x;
    for (int idx = t; idx < 64 * NCL; idx += 256) {
        Ws[(idx / NCL) * 44 + (idx % NCL)] = __ldg(W2 + idx);
    }
    if (t < NCL) { as_s[t] = __ldg(a_s + t); ad_s[t] = __ldg(a_d + t); }
    __syncthreads();
    int wid = t >> 5, l = t & 31;
    int base = blockIdx.x * 32 + wid * 4;
    const int lb = (l < 9) ? (32 + l) : 43;

#pragma unroll
    for (int n = 0; n < 4; n++) {
        unsigned hv = __ldg((const unsigned*)h1e + (base + n) * 32 + l);
        hs[wid][n][l] = __half22float2(*(__half2*)&hv);
    }
    __syncwarp();

    float acc0[4] = {0.f, 0.f, 0.f, 0.f};
    float acc1[4] = {0.f, 0.f, 0.f, 0.f};
#pragma unroll 8
    for (int j = 0; j < 32; j++) {
        float w0  = Ws[(2 * j) * 44 + l];
        float w1  = Ws[(2 * j + 1) * 44 + l];
        float w0b = Ws[(2 * j) * 44 + lb];
        float w1b = Ws[(2 * j + 1) * 44 + lb];
#pragma unroll
        for (int n = 0; n < 4; n++) {
            float2 p = hs[wid][n][j];
            acc0[n] += p.x * w0  + p.y * w1;
            acc1[n] += p.x * w0b + p.y * w1b;
        }
    }

#pragma unroll
    for (int n = 0; n < 4; n++) {
        int node = base + n;
        float sp = acc0[n] * as_s[l] + ((l < 9) ? acc1[n] * as_s[lb] : 0.f);
        float dp = acc0[n] * ad_s[l] + ((l < 9) ? acc1[n] * ad_s[lb] : 0.f);
#pragma unroll
        for (int o = 16; o; o >>= 1) {
            sp += __shfl_xor_sync(0xffffffffu, sp, o);
            dp += __shfl_xor_sync(0xffffffffu, dp, o);
        }
        if (l == 0) { s2g[node] = sp; d2g[node] = dp; }
        float x0 = __shfl_sync(0xffffffffu, acc0[n], (2 * l) & 31);
        float y0 = __shfl_sync(0xffffffffu, acc1[n], (2 * l) & 31);
        float x1 = __shfl_sync(0xffffffffu, acc0[n], (2 * l + 1) & 31);
        float y1 = __shfl_sync(0xffffffffu, acc1[n], (2 * l + 1) & 31);
        float e0 = (2 * l     < 32) ? x0 : y0;
        float e1 = (2 * l + 1 < 32) ? x1 : y1;
        if (l < 21) {
            if (l == 20) e1 = 0.f;  // channel 41 pad
            ((__half2*)(h2h + node * H2S))[l] = __floats2half2_rn(e0, e1);
        }
    }
}

// ---------------- agg2: warp per dst, MLP-16 batched gathers, log_softmax ----
__global__ __launch_bounds__(256, 5) void agg2_kernel(const float* __restrict__ b2,
                                                      float* __restrict__ out) {
    int w = blockIdx.x * 8 + (threadIdx.x >> 5);
    if (w >= NN) return;
    int l = threadIdx.x & 31;
    int dst = w;
    int li = l < 24 ? l : 23;
    float dv = __ldg(d2g + dst);

    float ws = __expf(lrelu(__ldg(s2g + dst) + dv));
    unsigned hv = __ldg((const unsigned*)h2h + dst * 32 + li);
    float2 f = __half22float2(*(__half2*)&hv);
    float a0 = ws * f.x, a1 = ws * f.y, z = ws;

    int beg = __ldg(offg + dst), end = __ldg(offg + dst + 1);
    for (int k0 = beg; k0 < end; k0 += 32) {
        int n = end - k0; if (n > 32) n = 32;
        int srcl = __ldg(csrg + k0 + (l < n ? l : n - 1));
        float wall = __expf(lrelu(__ldg(s2g + srcl) + dv));

#pragma unroll
        for (int gg = 0; gg < 2; gg++) {
            if (gg * 16 >= n) break;
            unsigned hb[16];
#pragma unroll
            for (int u = 0; u < 16; u++) {
                int i = gg * 16 + u; if (i >= n) i = n - 1;
                int src = __shfl_sync(0xffffffffu, srcl, i);
                hb[u] = __ldg((const unsigned*)h2h + src * 32 + li);
            }
#pragma unroll
            for (int u = 0; u < 16; u++) {
                int i = gg * 16 + u;
                float we = __shfl_sync(0xffffffffu, wall, i & 31);
                if (i >= n) we = 0.f;
                float2 g = __half22float2(*(__half2*)&hb[u]);
                a0 += we * g.x; a1 += we * g.y; z += we;
            }
        }
    }
    float inv = 1.0f / (z + 1e-16f);
    int c0 = 2 * l, c1 = 2 * l + 1;
    float v0 = (c0 < NCL) ? a0 * inv + __ldg(b2 + c0) : -1e30f;
    float v1 = (c1 < NCL) ? a1 * inv + __ldg(b2 + c1) : -1e30f;
    float m = fmaxf(v0, v1);
#pragma unroll
    for (int o = 16; o; o >>= 1) m = fmaxf(m, __shfl_xor_sync(0xffffffffu, m, o));
    float se = ((c0 < NCL) ? __expf(v0 - m) : 0.f) + ((c1 < NCL) ? __expf(v1 - m) : 0.f);
#pragma unroll
    for (int o = 16; o; o >>= 1) se += __shfl_xor_sync(0xffffffffu, se, o);
    float ls = m + logf(se);
    if (c0 < NCL) out[dst * NCL + c0] = v0 - ls;
    if (c1 < NCL) out[dst * NCL + c1] = v1 - ls;
}

// ---------------- launch ------------------------------------------------------
extern "C" void kernel_launch(void* const* d_in, const int* in_sizes, int n_in,
                              void* d_out, int out_size) {
    const float* x      = (const float*)d_in[0];
    const int*   ei     = (const int*)d_in[1];
    const float* W1     = (const float*)d_in[2];
    const float* a_src1 = (const float*)d_in[3];
    const float* a_dst1 = (const float*)d_in[4];
    const float* b1     = (const float*)d_in[5];
    const float* W2     = (const float*)d_in[6];
    const float* a_src2 = (const float*)d_in[7];
    const float* a_dst2 = (const float*)d_in[8];
    const float* b2     = (const float*)d_in[9];
    float*       out    = (float*)d_out;

    static cudaStream_t s2 = nullptr;
    static cudaEvent_t  evA = nullptr, evB = nullptr;
    static void* cnt_ptr = nullptr;
    if (!s2) {
        cudaStreamCreateWithFlags(&s2, cudaStreamNonBlocking);
        cudaEventCreateWithFlags(&evA, cudaEventDisableTiming);
        cudaEventCreateWithFlags(&evB, cudaEventDisableTiming);
        cudaGetSymbolAddress(&cnt_ptr, cntg);
    }

    // fork: GEMM1 chain on s2, CSR chain on main stream
    cudaEventRecord(evA, 0);
    cudaStreamWaitEvent(s2, evA, 0);
    prep_kernel<<<1, 256, 0, s2>>>(W1, a_src1, a_dst1);
    gemm1_tc<<<(NN + 127) / 128, 256, 0, s2>>>(x);
    cudaEventRecord(evB, s2);

    cudaMemsetAsync(cnt_ptr, 0, NN * sizeof(int), 0);
    hist_kernel<<<NE / 4 / 256, 256>>>(ei);
    scan1_kernel<<<(NN + 1023) / 1024, 1024>>>();
    scanF_kernel<<<(NN + 1023) / 1024, 1024>>>();
    scatter_kernel<<<NE / 4 / 256, 256>>>(ei);

    cudaStreamWaitEvent(0, evB, 0);   // join
    agg1_kernel<<<(NN + 7) / 8, 256>>>(b1);
    gemm2_kernel<<<(NN + 31) / 32, 256>>>(W2, a_src2, a_dst2);
    agg2_kernel<<<(NN + 7) / 8, 256>>>(b2, out);
}

// round 15
// speedup vs baseline: 1.1535x; 1.1535x over previous
#include <cuda_runtime.h>
#include <cuda_fp16.h>

#define NN   100000
#define NE   3200000
#define FIN  256
#define HC   64      // H1*C1
#define NH   8
#define NCL  41
#define H2S  64      // h2h row stride in halves (128B aligned rows)

// ---------------- scratch (static device globals; no runtime alloc) ----------
__device__ __align__(256) __half Wcg[FIN * 80];    // combined W1 | W1*a_src | W1*a_dst (fp16)
__device__ __align__(256) __half h1h[NN * HC];     // fp16 gemm1 out for agg1 gathers
__device__ __align__(256) __half h1e[NN * HC];     // fp16 ELU output (agg1 -> gemm2)
__device__ __align__(256) float  s1g[NN * NH];
__device__ __align__(256) float  d1g[NN * NH];
__device__ __align__(256) __half h2h[NN * H2S];    // fp16 layer2 features (ch 42..63 stay 0)
__device__ __align__(256) float  s2g[NN];
__device__ __align__(256) float  d2g[NN];
__device__ __align__(256) int    cntg[NN];
__device__ __align__(256) int    offg[NN + 1];
__device__ __align__(256) int    rankg[NE];
__device__ __align__(256) int    csrg[NE];
__device__ __align__(256) int    bsumg[128];

__device__ __forceinline__ float lrelu(float x) { return fmaxf(x, 0.2f * x); }

// ---------------- prep: build combined fp16 weight matrix --------------------
__global__ void prep_kernel(const float* __restrict__ W1, const float* __restrict__ as1,
                            const float* __restrict__ ad1) {
    int k = blockIdx.x * blockDim.x + threadIdx.x;
    if (k >= FIN) return;
    const float* row = W1 + k * 64;
    __half* out = Wcg + k * 80;
#pragma unroll
    for (int c = 0; c < 64; c++) out[c] = __float2half(row[c]);
#pragma unroll
    for (int h = 0; h < 8; h++) {
        float s = 0.f, d = 0.f;
#pragma unroll
        for (int c = 0; c < 8; c++) {
            float v = row[h * 8 + c];
            s += v * __ldg(as1 + h * 8 + c);
            d += v * __ldg(ad1 + h * 8 + c);
        }
        out[64 + h] = __float2half(s);
        out[72 + h] = __float2half(d);
    }
}

// ---------------- GEMM1 (tensor cores): [h1h | s1 | d1] = x @ Wc --------------
__device__ __forceinline__ void ldsm4(unsigned& r0, unsigned& r1, unsigned& r2, unsigned& r3,
                                      unsigned addr) {
    asm volatile("ldmatrix.sync.aligned.m8n8.x4.shared.b16 {%0,%1,%2,%3},[%4];"
                 : "=r"(r0), "=r"(r1), "=r"(r2), "=r"(r3) : "r"(addr));
}
__device__ __forceinline__ void ldsm4t(unsigned& r0, unsigned& r1, unsigned& r2, unsigned& r3,
                                       unsigned addr) {
    asm volatile("ldmatrix.sync.aligned.m8n8.x4.trans.shared.b16 {%0,%1,%2,%3},[%4];"
                 : "=r"(r0), "=r"(r1), "=r"(r2), "=r"(r3) : "r"(addr));
}
__device__ __forceinline__ void mma16816(float* c, unsigned a0, unsigned a1, unsigned a2,
                                         unsigned a3, unsigned b0, unsigned b1) {
    asm volatile("mma.sync.aligned.m16n8k16.row.col.f32.f16.f16.f32 "
                 "{%0,%1,%2,%3},{%4,%5,%6,%7},{%8,%9},{%0,%1,%2,%3};"
                 : "+f"(c[0]), "+f"(c[1]), "+f"(c[2]), "+f"(c[3])
                 : "r"(a0), "r"(a1), "r"(a2), "r"(a3), "r"(b0), "r"(b1));
}

__global__ __launch_bounds__(256) void gemm1_tc(const float* __restrict__ x) {
    __shared__ __align__(16) __half As[128 * 72];
    __shared__ __align__(16) __half Bs[128 * 88];
    int t = threadIdx.x, w = t >> 5, lane = t & 31;
    int m0 = blockIdx.x * 128;

    float acc[10][4];
#pragma unroll
    for (int i = 0; i < 10; i++)
#pragma unroll
        for (int j = 0; j < 4; j++) acc[i][j] = 0.f;

    int arow = t >> 1;
    int ac32 = (t & 1) << 5;
    int gr = m0 + arow; if (gr >= NN) gr = NN - 1;
    const float* xrow = x + (long long)gr * FIN;

    unsigned aBase = (unsigned)__cvta_generic_to_shared(
        &As[((w << 4) + (lane & 15)) * 72 + ((lane >> 4) << 3)]);
    unsigned bRowOff = ((lane & 15) * 88 + ((lane >> 4) << 3)) * 2;

    for (int kb = 0; kb < 2; kb++) {
        __syncthreads();
        for (int idx = t; idx < 128 * 10; idx += 256) {
            int krow = idx / 10, seg = idx % 10;
            *(uint4*)&Bs[krow * 88 + seg * 8] =
                *(const uint4*)&Wcg[(kb * 128 + krow) * 80 + seg * 8];
        }
        for (int c = 0; c < 2; c++) {
            __syncthreads();
            int kc = kb * 128 + c * 64 + ac32;
            uint4 pk[4];
#pragma unroll
            for (int q = 0; q < 4; q++) {
                float4 v0 = __ldg((const float4*)(xrow + kc + q * 8));
                float4 v1 = __ldg((const float4*)(xrow + kc + q * 8 + 4));
                __half2 p0 = __floats2half2_rn(v0.x, v0.y);
                __half2 p1 = __floats2half2_rn(v0.z, v0.w);
                __half2 p2 = __floats2half2_rn(v1.x, v1.y);
                __half2 p3 = __floats2half2_rn(v1.z, v1.w);
                pk[q] = make_uint4(*(unsigned*)&p0, *(unsigned*)&p1,
                                   *(unsigned*)&p2, *(unsigned*)&p3);
            }
#pragma unroll
            for (int q = 0; q < 4; q++)
                *(uint4*)&As[arow * 72 + ac32 + q * 8] = pk[q];
            __syncthreads();
#pragma unroll
            for (int ks = 0; ks < 4; ks++) {
                unsigned a0, a1, a2, a3;
                ldsm4(a0, a1, a2, a3, aBase + ks * 32);
                unsigned bAddr = (unsigned)__cvta_generic_to_shared(
                                     &Bs[(c * 64 + ks * 16) * 88]) + bRowOff;
#pragma unroll
                for (int bt = 0; bt < 5; bt++) {
                    unsigned b0, b1, b2, b3;
                    ldsm4t(b0, b1, b2, b3, bAddr + bt * 32);
                    mma16816(acc[bt * 2],     a0, a1, a2, a3, b0, b1);
                    mma16816(acc[bt * 2 + 1], a0, a1, a2, a3, b2, b3);
                }
            }
        }
    }

    int r0 = m0 + (w << 4) + (lane >> 2);
    int r1 = r0 + 8;
    int cq = (lane & 3) << 1;
#pragma unroll
    for (int nt = 0; nt < 8; nt++) {
        int col = nt * 8 + cq;
        if (r0 < NN) *(__half2*)(h1h + r0 * 64 + col) = __floats2half2_rn(acc[nt][0], acc[nt][1]);
        if (r1 < NN) *(__half2*)(h1h + r1 * 64 + col) = __floats2half2_rn(acc[nt][2], acc[nt][3]);
    }
    if (r0 < NN) {
        s1g[r0 * 8 + cq] = acc[8][0]; s1g[r0 * 8 + cq + 1] = acc[8][1];
        d1g[r0 * 8 + cq] = acc[9][0]; d1g[r0 * 8 + cq + 1] = acc[9][1];
    }
    if (r1 < NN) {
        s1g[r1 * 8 + cq] = acc[8][2]; s1g[r1 * 8 + cq + 1] = acc[8][3];
        d1g[r1 * 8 + cq] = acc[9][2]; d1g[r1 * 8 + cq + 1] = acc[9][3];
    }
}

// ---------------- CSR build ---------------------------------------------------
__global__ void hist_kernel(const int* __restrict__ ei) {
    int e4 = blockIdx.x * blockDim.x + threadIdx.x;
    if (e4 * 4 >= NE) return;
    int4 d = __ldg((const int4*)(ei + NE) + e4);
    int4 r;
    r.x = atomicAdd(cntg + d.x, 1);
    r.y = atomicAdd(cntg + d.y, 1);
    r.z = atomicAdd(cntg + d.z, 1);
    r.w = atomicAdd(cntg + d.w, 1);
    ((int4*)rankg)[e4] = r;
}

__global__ void scan1_kernel() {
    __shared__ int wsum[32];
    int t = threadIdx.x, lane = t & 31, wd = t >> 5;
    int i = blockIdx.x * 1024 + t;
    int v = (i < NN) ? cntg[i] : 0;
    int x = v;
#pragma unroll
    for (int o = 1; o < 32; o <<= 1) {
        int y = __shfl_up_sync(0xffffffffu, x, o);
        if (lane >= o) x += y;
    }
    if (lane == 31) wsum[wd] = x;
    __syncthreads();
    if (wd == 0) {
        int y = wsum[lane];
#pragma unroll
        for (int o = 1; o < 32; o <<= 1) {
            int z = __shfl_up_sync(0xffffffffu, y, o);
            if (lane >= o) y += z;
        }
        wsum[lane] = y;
    }
    __syncthreads();
    int excl = x - v + (wd ? wsum[wd - 1] : 0);
    if (i < NN) offg[i] = excl;
    if (t == 1023) bsumg[blockIdx.x] = excl + v;
}

__global__ void scan2_kernel() {
    __shared__ int ws[4];
    int t = threadIdx.x, lane = t & 31, wd = t >> 5;
    int v = (t < 98) ? bsumg[t] : 0;
    int x = v;
#pragma unroll
    for (int o = 1; o < 32; o <<= 1) {
        int y = __shfl_up_sync(0xffffffffu, x, o);
        if (lane >= o) x += y;
    }
    if (lane == 31) ws[wd] = x;
    __syncthreads();
    int add = 0;
    for (int k = 0; k < wd; k++) add += ws[k];
    int excl = x - v + add;
    if (t < 98) bsumg[t] = excl;
    if (t == 127) offg[NN] = excl + v;
}

__global__ void scan3_kernel() {
    int i = blockIdx.x * 1024 + threadIdx.x;
    if (i < NN) offg[i] += bsumg[blockIdx.x];
}

__global__ void scatter_kernel(const int* __restrict__ ei) {
    int e4 = blockIdx.x * blockDim.x + threadIdx.x;
    if (e4 * 4 >= NE) return;
    int4 s = __ldg((const int4*)ei + e4);
    int4 d = __ldg((const int4*)(ei + NE) + e4);
    int4 r = ((const int4*)rankg)[e4];
    csrg[__ldg(offg + d.x) + r.x] = s.x;
    csrg[__ldg(offg + d.y) + r.y] = s.y;
    csrg[__ldg(offg + d.z) + r.z] = s.z;
    csrg[__ldg(offg + d.w) + r.w] = s.w;
}

// ---------------- agg1: warp per dst, MLP-8 batched gathers -------------------
__global__ __launch_bounds__(256, 5) void agg1_kernel(const float* __restrict__ b1) {
    int w = blockIdx.x * 8 + (threadIdx.x >> 5);
    if (w >= NN) return;
    int l = threadIdx.x & 31;
    int dst = w;
    int hw = l & 7, q = l >> 3;
    float dl = __ldg(d1g + dst * 8 + hw);

    float s8 = __ldg(s1g + dst * 8 + hw);
    float w8 = __expf(lrelu(s8 + dl));
    float ww = __shfl_sync(0xffffffffu, w8, l >> 2);
    unsigned hv = __ldg((const unsigned*)h1h + dst * 32 + l);
    float2 f = __half22float2(*(__half2*)&hv);
    float a0 = ww * f.x, a1 = ww * f.y, z = ww;

    int beg = __ldg(offg + dst), end = __ldg(offg + dst + 1);
    for (int k0 = beg; k0 < end; k0 += 32) {
        int n = end - k0; if (n > 32) n = 32;
        int srcl = __ldg(csrg + k0 + (l < n ? l : n - 1));

        float wreg[8];
#pragma unroll
        for (int g = 0; g < 8; g++) {
            int e = g * 4 + q; if (e >= n) e = n - 1;
            int sw_ = __shfl_sync(0xffffffffu, srcl, e);
            wreg[g] = __expf(lrelu(__ldg(s1g + sw_ * 8 + hw) + dl));
        }

#pragma unroll
        for (int gg = 0; gg < 4; gg++) {
            if (gg * 8 >= n) break;   // warp-uniform
            unsigned hb[8];
#pragma unroll
            for (int u = 0; u < 8; u++) {
                int i = gg * 8 + u; if (i >= n) i = n - 1;
                int src = __shfl_sync(0xffffffffu, srcl, i);
                hb[u] = __ldg((const unsigned*)h1h + src * 32 + l);
            }
#pragma unroll
            for (int u = 0; u < 8; u++) {
                int i = gg * 8 + u;
                float we = __shfl_sync(0xffffffffu, wreg[(gg * 8 + u) >> 2],
                                       ((u & 3) << 3) + (l >> 2));
                if (i >= n) we = 0.f;
                float2 g2 = __half22float2(*(__half2*)&hb[u]);
                a0 += we * g2.x; a1 += we * g2.y; z += we;
            }
        }
    }
    float inv = 1.0f / (z + 1e-16f);
    float v0 = a0 * inv + __ldg(b1 + 2 * l);
    float v1 = a1 * inv + __ldg(b1 + 2 * l + 1);
    v0 = v0 > 0.f ? v0 : expm1f(v0);
    v1 = v1 > 0.f ? v1 : expm1f(v1);
    ((__half2*)(h1e + dst * 64))[l] = __floats2half2_rn(v0, v1);
}

// ---------------- gemm2: 4 nodes per warp, smem-staged h, W2 LDS shared ------
__global__ void gemm2_kernel(const float* __restrict__ W2, const float* __restrict__ a_s,
                             const float* __restrict__ a_d) {
    __shared__ float  Ws[64 * 44];
    __shared__ float  as_s[44], ad_s[44];
    __shared__ float2 hs[8][4][32];
    int t = threadIdx.x;
    for (int idx = t; idx < 64 * NCL; idx += 256) {
        Ws[(idx / NCL) * 44 + (idx % NCL)] = __ldg(W2 + idx);
    }
    if (t < NCL) { as_s[t] = __ldg(a_s + t); ad_s[t] = __ldg(a_d + t); }
    __syncthreads();
    int wid = t >> 5, l = t & 31;
    int base = blockIdx.x * 32 + wid * 4;
    const int lb = (l < 9) ? (32 + l) : 43;

#pragma unroll
    for (int n = 0; n < 4; n++) {
        unsigned hv = __ldg((const unsigned*)h1e + (base + n) * 32 + l);
        hs[wid][n][l] = __half22float2(*(__half2*)&hv);
    }
    __syncwarp();

    float acc0[4] = {0.f, 0.f, 0.f, 0.f};
    float acc1[4] = {0.f, 0.f, 0.f, 0.f};
#pragma unroll 8
    for (int j = 0; j < 32; j++) {
        float w0  = Ws[(2 * j) * 44 + l];
        float w1  = Ws[(2 * j + 1) * 44 + l];
        float w0b = Ws[(2 * j) * 44 + lb];
        float w1b = Ws[(2 * j + 1) * 44 + lb];
#pragma unroll
        for (int n = 0; n < 4; n++) {
            float2 p = hs[wid][n][j];
            acc0[n] += p.x * w0  + p.y * w1;
            acc1[n] += p.x * w0b + p.y * w1b;
        }
    }

#pragma unroll
    for (int n = 0; n < 4; n++) {
        int node = base + n;
        float sp = acc0[n] * as_s[l] + ((l < 9) ? acc1[n] * as_s[lb] : 0.f);
        float dp = acc0[n] * ad_s[l] + ((l < 9) ? acc1[n] * ad_s[lb] : 0.f);
#pragma unroll
        for (int o = 16; o; o >>= 1) {
            sp += __shfl_xor_sync(0xffffffffu, sp, o);
            dp += __shfl_xor_sync(0xffffffffu, dp, o);
        }
        if (l == 0) { s2g[node] = sp; d2g[node] = dp; }
        float x0 = __shfl_sync(0xffffffffu, acc0[n], (2 * l) & 31);
        float y0 = __shfl_sync(0xffffffffu, acc1[n], (2 * l) & 31);
        float x1 = __shfl_sync(0xffffffffu, acc0[n], (2 * l + 1) & 31);
        float y1 = __shfl_sync(0xffffffffu, acc1[n], (2 * l + 1) & 31);
        float e0 = (2 * l     < 32) ? x0 : y0;
        float e1 = (2 * l + 1 < 32) ? x1 : y1;
        if (l < 21) {
            if (l == 20) e1 = 0.f;  // channel 41 pad
            ((__half2*)(h2h + node * H2S))[l] = __floats2half2_rn(e0, e1);
        }
    }
}

// ---------------- agg2: warp per dst, MLP-8 batched gathers, log_softmax -----
__global__ __launch_bounds__(256, 6) void agg2_kernel(const float* __restrict__ b2,
                                                      float* __restrict__ out) {
    int w = blockIdx.x * 8 + (threadIdx.x >> 5);
    if (w >= NN) return;
    int l = threadIdx.x & 31;
    int dst = w;
    int li = l < 24 ? l : 23;
    float dv = __ldg(d2g + dst);

    float ws = __expf(lrelu(__ldg(s2g + dst) + dv));
    unsigned hv = __ldg((const unsigned*)h2h + dst * 32 + li);
    float2 f = __half22float2(*(__half2*)&hv);
    float a0 = ws * f.x, a1 = ws * f.y, z = ws;

    int beg = __ldg(offg + dst), end = __ldg(offg + dst + 1);
    for (int k0 = beg; k0 < end; k0 += 32) {
        int n = end - k0; if (n > 32) n = 32;
        int srcl = __ldg(csrg + k0 + (l < n ? l : n - 1));
        float wall = __expf(lrelu(__ldg(s2g + srcl) + dv));

#pragma unroll
        for (int gg = 0; gg < 4; gg++) {
            if (gg * 8 >= n) break;
            unsigned hb[8];
#pragma unroll
            for (int u = 0; u < 8; u++) {
                int i = gg * 8 + u; if (i >= n) i = n - 1;
                int src = __shfl_sync(0xffffffffu, srcl, i);
                hb[u] = __ldg((const unsigned*)h2h + src * 32 + li);
            }
#pragma unroll
            for (int u = 0; u < 8; u++) {
                int i = gg * 8 + u;
                float we = __shfl_sync(0xffffffffu, wall, (gg * 8 + u) & 31);
                if (i >= n) we = 0.f;
                float2 g = __half22float2(*(__half2*)&hb[u]);
                a0 += we * g.x; a1 += we * g.y; z += we;
            }
        }
    }
    float inv = 1.0f / (z + 1e-16f);
    int c0 = 2 * l, c1 = 2 * l + 1;
    float v0 = (c0 < NCL) ? a0 * inv + __ldg(b2 + c0) : -1e30f;
    float v1 = (c1 < NCL) ? a1 * inv + __ldg(b2 + c1) : -1e30f;
    float m = fmaxf(v0, v1);
#pragma unroll
    for (int o = 16; o; o >>= 1) m = fmaxf(m, __shfl_xor_sync(0xffffffffu, m, o));
    float se = ((c0 < NCL) ? __expf(v0 - m) : 0.f) + ((c1 < NCL) ? __expf(v1 - m) : 0.f);
#pragma unroll
    for (int o = 16; o; o >>= 1) se += __shfl_xor_sync(0xffffffffu, se, o);
    float ls = m + logf(se);
    if (c0 < NCL) out[dst * NCL + c0] = v0 - ls;
    if (c1 < NCL) out[dst * NCL + c1] = v1 - ls;
}

// ---------------- launch ------------------------------------------------------
extern "C" void kernel_launch(void* const* d_in, const int* in_sizes, int n_in,
                              void* d_out, int out_size) {
    const float* x      = (const float*)d_in[0];
    const int*   ei     = (const int*)d_in[1];
    const float* W1     = (const float*)d_in[2];
    const float* a_src1 = (const float*)d_in[3];
    const float* a_dst1 = (const float*)d_in[4];
    const float* b1     = (const float*)d_in[5];
    const float* W2     = (const float*)d_in[6];
    const float* a_src2 = (const float*)d_in[7];
    const float* a_dst2 = (const float*)d_in[8];
    const float* b2     = (const float*)d_in[9];
    float*       out    = (float*)d_out;

    static cudaStream_t s2 = nullptr;
    static cudaEvent_t  evA = nullptr, evB = nullptr;
    static void* cnt_ptr = nullptr;
    if (!s2) {
        cudaStreamCreateWithFlags(&s2, cudaStreamNonBlocking);
        cudaEventCreateWithFlags(&evA, cudaEventDisableTiming);
        cudaEventCreateWithFlags(&evB, cudaEventDisableTiming);
        cudaGetSymbolAddress(&cnt_ptr, cntg);
    }

    // fork: GEMM1 chain on s2, CSR chain on main stream
    cudaEventRecord(evA, 0);
    cudaStreamWaitEvent(s2, evA, 0);
    prep_kernel<<<1, 256, 0, s2>>>(W1, a_src1, a_dst1);
    gemm1_tc<<<(NN + 127) / 128, 256, 0, s2>>>(x);
    cudaEventRecord(evB, s2);

    cudaMemsetAsync(cnt_ptr, 0, NN * sizeof(int), 0);
    hist_kernel<<<NE / 4 / 256, 256>>>(ei);
    scan1_kernel<<<(NN + 1023) / 1024, 1024>>>();
    scan2_kernel<<<1, 128>>>();
    scan3_kernel<<<(NN + 1023) / 1024, 1024>>>();
    scatter_kernel<<<NE / 4 / 256, 256>>>(ei);

    cudaStreamWaitEvent(0, evB, 0);   // join
    agg1_kernel<<<(NN + 7) / 8, 256>>>(b1);
    gemm2_kernel<<<(NN + 31) / 32, 256>>>(W2, a_src2, a_dst2);
    agg2_kernel<<<(NN + 7) / 8, 256>>>(b2, out);
}

// round 16
// speedup vs baseline: 1.2633x; 1.0951x over previous
#include <cuda_runtime.h>
#include <cuda_fp16.h>

#define NN   100000
#define NE   3200000
#define FIN  256
#define HC   64      // H1*C1
#define NH   8
#define NCL  41
#define H2S  64      // h2h row stride in halves (128B aligned rows)

// ---------------- scratch (static device globals; no runtime alloc) ----------
__device__ __align__(256) __half Wcg[FIN * 80];    // combined W1 | W1*a_src | W1*a_dst (fp16)
__device__ __align__(256) __half h1h[NN * HC];     // fp16 gemm1 out for agg1 gathers
__device__ __align__(256) __half h1e[NN * HC];     // fp16 ELU output (agg1 -> gemm2)
__device__ __align__(256) float  s1g[NN * NH];
__device__ __align__(256) float  d1g[NN * NH];
__device__ __align__(256) __half h2h[NN * H2S];    // fp16 layer2 features (ch 42..63 stay 0)
__device__ __align__(256) float  s2g[NN];
__device__ __align__(256) float  d2g[NN];
__device__ __align__(256) int    cntg[NN];
__device__ __align__(256) int    offg[NN + 1];
__device__ __align__(256) int    rankg[NE];
__device__ __align__(256) int    csrg[NE];
__device__ __align__(256) int    bsumg[128];

__device__ __forceinline__ float lrelu(float x) { return fmaxf(x, 0.2f * x); }

#define CPA16(sa, ga) \
    asm volatile("cp.async.cg.shared.global [%0], [%1], 16;" :: "r"(sa), "l"(ga) : "memory")
#define CPA_COMMIT()  asm volatile("cp.async.commit_group;" ::: "memory")
#define CPA_WAIT0()   asm volatile("cp.async.wait_group 0;" ::: "memory")

// ---------------- prep: build combined fp16 weight matrix --------------------
__global__ void prep_kernel(const float* __restrict__ W1, const float* __restrict__ as1,
                            const float* __restrict__ ad1) {
    int k = blockIdx.x * blockDim.x + threadIdx.x;
    if (k >= FIN) return;
    const float* row = W1 + k * 64;
    __half* out = Wcg + k * 80;
#pragma unroll
    for (int c = 0; c < 64; c++) out[c] = __float2half(row[c]);
#pragma unroll
    for (int h = 0; h < 8; h++) {
        float s = 0.f, d = 0.f;
#pragma unroll
        for (int c = 0; c < 8; c++) {
            float v = row[h * 8 + c];
            s += v * __ldg(as1 + h * 8 + c);
            d += v * __ldg(ad1 + h * 8 + c);
        }
        out[64 + h] = __float2half(s);
        out[72 + h] = __float2half(d);
    }
}

// ---------------- GEMM1 (tensor cores): [h1h | s1 | d1] = x @ Wc --------------
__device__ __forceinline__ void ldsm4(unsigned& r0, unsigned& r1, unsigned& r2, unsigned& r3,
                                      unsigned addr) {
    asm volatile("ldmatrix.sync.aligned.m8n8.x4.shared.b16 {%0,%1,%2,%3},[%4];"
                 : "=r"(r0), "=r"(r1), "=r"(r2), "=r"(r3) : "r"(addr));
}
__device__ __forceinline__ void ldsm4t(unsigned& r0, unsigned& r1, unsigned& r2, unsigned& r3,
                                       unsigned addr) {
    asm volatile("ldmatrix.sync.aligned.m8n8.x4.trans.shared.b16 {%0,%1,%2,%3},[%4];"
                 : "=r"(r0), "=r"(r1), "=r"(r2), "=r"(r3) : "r"(addr));
}
__device__ __forceinline__ void mma16816(float* c, unsigned a0, unsigned a1, unsigned a2,
                                         unsigned a3, unsigned b0, unsigned b1) {
    asm volatile("mma.sync.aligned.m16n8k16.row.col.f32.f16.f16.f32 "
                 "{%0,%1,%2,%3},{%4,%5,%6,%7},{%8,%9},{%0,%1,%2,%3};"
                 : "+f"(c[0]), "+f"(c[1]), "+f"(c[2]), "+f"(c[3])
                 : "r"(a0), "r"(a1), "r"(a2), "r"(a3), "r"(b0), "r"(b1));
}

__global__ __launch_bounds__(256) void gemm1_tc(const float* __restrict__ x) {
    __shared__ __align__(16) __half As[128 * 72];
    __shared__ __align__(16) __half Bs[128 * 88];
    int t = threadIdx.x, w = t >> 5, lane = t & 31;
    int m0 = blockIdx.x * 128;

    float acc[10][4];
#pragma unroll
    for (int i = 0; i < 10; i++)
#pragma unroll
        for (int j = 0; j < 4; j++) acc[i][j] = 0.f;

    int arow = t >> 1;
    int ac32 = (t & 1) << 5;
    int gr = m0 + arow; if (gr >= NN) gr = NN - 1;
    const float* xrow = x + (long long)gr * FIN;

    unsigned aBase = (unsigned)__cvta_generic_to_shared(
        &As[((w << 4) + (lane & 15)) * 72 + ((lane >> 4) << 3)]);
    unsigned bRowOff = ((lane & 15) * 88 + ((lane >> 4) << 3)) * 2;

    for (int kb = 0; kb < 2; kb++) {
        __syncthreads();
        for (int idx = t; idx < 128 * 10; idx += 256) {
            int krow = idx / 10, seg = idx % 10;
            *(uint4*)&Bs[krow * 88 + seg * 8] =
                *(const uint4*)&Wcg[(kb * 128 + krow) * 80 + seg * 8];
        }
        for (int c = 0; c < 2; c++) {
            __syncthreads();
            int kc = kb * 128 + c * 64 + ac32;
            uint4 pk[4];
#pragma unroll
            for (int q = 0; q < 4; q++) {
                float4 v0 = __ldg((const float4*)(xrow + kc + q * 8));
                float4 v1 = __ldg((const float4*)(xrow + kc + q * 8 + 4));
                __half2 p0 = __floats2half2_rn(v0.x, v0.y);
                __half2 p1 = __floats2half2_rn(v0.z, v0.w);
                __half2 p2 = __floats2half2_rn(v1.x, v1.y);
                __half2 p3 = __floats2half2_rn(v1.z, v1.w);
                pk[q] = make_uint4(*(unsigned*)&p0, *(unsigned*)&p1,
                                   *(unsigned*)&p2, *(unsigned*)&p3);
            }
#pragma unroll
            for (int q = 0; q < 4; q++)
                *(uint4*)&As[arow * 72 + ac32 + q * 8] = pk[q];
            __syncthreads();
#pragma unroll
            for (int ks = 0; ks < 4; ks++) {
                unsigned a0, a1, a2, a3;
                ldsm4(a0, a1, a2, a3, aBase + ks * 32);
                unsigned bAddr = (unsigned)__cvta_generic_to_shared(
                                     &Bs[(c * 64 + ks * 16) * 88]) + bRowOff;
#pragma unroll
                for (int bt = 0; bt < 5; bt++) {
                    unsigned b0, b1, b2, b3;
                    ldsm4t(b0, b1, b2, b3, bAddr + bt * 32);
                    mma16816(acc[bt * 2],     a0, a1, a2, a3, b0, b1);
                    mma16816(acc[bt * 2 + 1], a0, a1, a2, a3, b2, b3);
                }
            }
        }
    }

    int r0 = m0 + (w << 4) + (lane >> 2);
    int r1 = r0 + 8;
    int cq = (lane & 3) << 1;
#pragma unroll
    for (int nt = 0; nt < 8; nt++) {
        int col = nt * 8 + cq;
        if (r0 < NN) *(__half2*)(h1h + r0 * 64 + col) = __floats2half2_rn(acc[nt][0], acc[nt][1]);
        if (r1 < NN) *(__half2*)(h1h + r1 * 64 + col) = __floats2half2_rn(acc[nt][2], acc[nt][3]);
    }
    if (r0 < NN) {
        s1g[r0 * 8 + cq] = acc[8][0]; s1g[r0 * 8 + cq + 1] = acc[8][1];
        d1g[r0 * 8 + cq] = acc[9][0]; d1g[r0 * 8 + cq + 1] = acc[9][1];
    }
    if (r1 < NN) {
        s1g[r1 * 8 + cq] = acc[8][2]; s1g[r1 * 8 + cq + 1] = acc[8][3];
        d1g[r1 * 8 + cq] = acc[9][2]; d1g[r1 * 8 + cq + 1] = acc[9][3];
    }
}

// ---------------- CSR build ---------------------------------------------------
__global__ void hist_kernel(const int* __restrict__ ei) {
    int e4 = blockIdx.x * blockDim.x + threadIdx.x;
    if (e4 * 4 >= NE) return;
    int4 d = __ldg((const int4*)(ei + NE) + e4);
    int4 r;
    r.x = atomicAdd(cntg + d.x, 1);
    r.y = atomicAdd(cntg + d.y, 1);
    r.z = atomicAdd(cntg + d.z, 1);
    r.w = atomicAdd(cntg + d.w, 1);
    ((int4*)rankg)[e4] = r;
}

__global__ void scan1_kernel() {
    __shared__ int wsum[32];
    int t = threadIdx.x, lane = t & 31, wd = t >> 5;
    int i = blockIdx.x * 1024 + t;
    int v = (i < NN) ? cntg[i] : 0;
    int x = v;
#pragma unroll
    for (int o = 1; o < 32; o <<= 1) {
        int y = __shfl_up_sync(0xffffffffu, x, o);
        if (lane >= o) x += y;
    }
    if (lane == 31) wsum[wd] = x;
    __syncthreads();
    if (wd == 0) {
        int y = wsum[lane];
#pragma unroll
        for (int o = 1; o < 32; o <<= 1) {
            int z = __shfl_up_sync(0xffffffffu, y, o);
            if (lane >= o) y += z;
        }
        wsum[lane] = y;
    }
    __syncthreads();
    int excl = x - v + (wd ? wsum[wd - 1] : 0);
    if (i < NN) offg[i] = excl;
    if (t == 1023) bsumg[blockIdx.x] = excl + v;
}

__global__ void scan2_kernel() {
    __shared__ int ws[4];
    int t = threadIdx.x, lane = t & 31, wd = t >> 5;
    int v = (t < 98) ? bsumg[t] : 0;
    int x = v;
#pragma unroll
    for (int o = 1; o < 32; o <<= 1) {
        int y = __shfl_up_sync(0xffffffffu, x, o);
        if (lane >= o) x += y;
    }
    if (lane == 31) ws[wd] = x;
    __syncthreads();
    int add = 0;
    for (int k = 0; k < wd; k++) add += ws[k];
    int excl = x - v + add;
    if (t < 98) bsumg[t] = excl;
    if (t == 127) offg[NN] = excl + v;
}

__global__ void scan3_kernel() {
    int i = blockIdx.x * 1024 + threadIdx.x;
    if (i < NN) offg[i] += bsumg[blockIdx.x];
}

__global__ void scatter_kernel(const int* __restrict__ ei) {
    int e4 = blockIdx.x * blockDim.x + threadIdx.x;
    if (e4 * 4 >= NE) return;
    int4 s = __ldg((const int4*)ei + e4);
    int4 d = __ldg((const int4*)(ei + NE) + e4);
    int4 r = ((const int4*)rankg)[e4];
    csrg[__ldg(offg + d.x) + r.x] = s.x;
    csrg[__ldg(offg + d.y) + r.y] = s.y;
    csrg[__ldg(offg + d.z) + r.z] = s.z;
    csrg[__ldg(offg + d.w) + r.w] = s.w;
}

// ---------------- agg1: warp per dst, cp.async smem-staged gathers (MLP-32) ---
__global__ __launch_bounds__(256, 5) void agg1_kernel(const float* __restrict__ b1) {
    __shared__ __align__(16) unsigned char buf[8][32 * 128];
    int wid = threadIdx.x >> 5;
    int w = blockIdx.x * 8 + wid;
    if (w >= NN) return;
    int l = threadIdx.x & 31;
    int dst = w;
    int hw = l & 7, q = l >> 3;
    unsigned bufw = (unsigned)__cvta_generic_to_shared(&buf[wid][0]);
    float dl = __ldg(d1g + dst * 8 + hw);

    float s8 = __ldg(s1g + dst * 8 + hw);
    float w8 = __expf(lrelu(s8 + dl));
    float ww = __shfl_sync(0xffffffffu, w8, l >> 2);
    unsigned hv = __ldg((const unsigned*)h1h + dst * 32 + l);
    float2 f = __half22float2(*(__half2*)&hv);
    float a0 = ww * f.x, a1 = ww * f.y, z = ww;

    int beg = __ldg(offg + dst), end = __ldg(offg + dst + 1);
    int seg = l & 7, egrp = l >> 3;
    for (int k0 = beg; k0 < end; k0 += 32) {
        int n = end - k0; if (n > 32) n = 32;
        int srcl = __ldg(csrg + k0 + (l < n ? l : n - 1));

        // issue 32 full-row copies (8 steps x 4 edges), MLP-32, no landing regs
#pragma unroll
        for (int st = 0; st < 8; st++) {
            int i = st * 4 + egrp;
            int ii = i < n ? i : n - 1;
            int src = __shfl_sync(0xffffffffu, srcl, ii);
            CPA16(bufw + i * 128 + seg * 16,
                  (const char*)(h1h + src * 64) + seg * 16);
        }
        CPA_COMMIT();

        // weight phase overlaps with copies in flight
        float wreg[8];
#pragma unroll
        for (int g = 0; g < 8; g++) {
            int e = g * 4 + q; if (e >= n) e = n - 1;
            int sw_ = __shfl_sync(0xffffffffu, srcl, e);
            wreg[g] = __expf(lrelu(__ldg(s1g + sw_ * 8 + hw) + dl));
        }

        CPA_WAIT0();
        __syncwarp();
        for (int i = 0; i < n; i++) {
            float we = __shfl_sync(0xffffffffu, wreg[i >> 2], ((i & 3) << 3) + (l >> 2));
            unsigned hword = *(const unsigned*)&buf[wid][i * 128 + l * 4];
            float2 g2 = __half22float2(*(__half2*)&hword);
            a0 += we * g2.x; a1 += we * g2.y; z += we;
        }
        __syncwarp();   // buf reuse (WAR) for next chunk
    }
    float inv = 1.0f / (z + 1e-16f);
    float v0 = a0 * inv + __ldg(b1 + 2 * l);
    float v1 = a1 * inv + __ldg(b1 + 2 * l + 1);
    v0 = v0 > 0.f ? v0 : expm1f(v0);
    v1 = v1 > 0.f ? v1 : expm1f(v1);
    ((__half2*)(h1e + dst * 64))[l] = __floats2half2_rn(v0, v1);
}

// ---------------- gemm2: 4 nodes per warp, smem-staged h, W2 LDS shared ------
__global__ void gemm2_kernel(const float* __restrict__ W2, const float* __restrict__ a_s,
                             const float* __restrict__ a_d) {
    __shared__ float  Ws[64 * 44];
    __shared__ float  as_s[44], ad_s[44];
    __shared__ float2 hs[8][4][32];
    int t = threadIdx.x;
    for (int idx = t; idx < 64 * NCL; idx += 256) {
        Ws[(idx / NCL) * 44 + (idx % NCL)] = __ldg(W2 + idx);
    }
    if (t < NCL) { as_s[t] = __ldg(a_s + t); ad_s[t] = __ldg(a_d + t); }
    __syncthreads();
    int wid = t >> 5, l = t & 31;
    int base = blockIdx.x * 32 + wid * 4;
    const int lb = (l < 9) ? (32 + l) : 43;

#pragma unroll
    for (int n = 0; n < 4; n++) {
        unsigned hv = __ldg((const unsigned*)h1e + (base + n) * 32 + l);
        hs[wid][n][l] = __half22float2(*(__half2*)&hv);
    }
    __syncwarp();

    float acc0[4] = {0.f, 0.f, 0.f, 0.f};
    float acc1[4] = {0.f, 0.f, 0.f, 0.f};
#pragma unroll 8
    for (int j = 0; j < 32; j++) {
        float w0  = Ws[(2 * j) * 44 + l];
        float w1  = Ws[(2 * j + 1) * 44 + l];
        float w0b = Ws[(2 * j) * 44 + lb];
        float w1b = Ws[(2 * j + 1) * 44 + lb];
#pragma unroll
        for (int n = 0; n < 4; n++) {
            float2 p = hs[wid][n][j];
            acc0[n] += p.x * w0  + p.y * w1;
            acc1[n] += p.x * w0b + p.y * w1b;
        }
    }

#pragma unroll
    for (int n = 0; n < 4; n++) {
        int node = base + n;
        float sp = acc0[n] * as_s[l] + ((l < 9) ? acc1[n] * as_s[lb] : 0.f);
        float dp = acc0[n] * ad_s[l] + ((l < 9) ? acc1[n] * ad_s[lb] : 0.f);
#pragma unroll
        for (int o = 16; o; o >>= 1) {
            sp += __shfl_xor_sync(0xffffffffu, sp, o);
            dp += __shfl_xor_sync(0xffffffffu, dp, o);
        }
        if (l == 0) { s2g[node] = sp; d2g[node] = dp; }
        float x0 = __shfl_sync(0xffffffffu, acc0[n], (2 * l) & 31);
        float y0 = __shfl_sync(0xffffffffu, acc1[n], (2 * l) & 31);
        float x1 = __shfl_sync(0xffffffffu, acc0[n], (2 * l + 1) & 31);
        float y1 = __shfl_sync(0xffffffffu, acc1[n], (2 * l + 1) & 31);
        float e0 = (2 * l     < 32) ? x0 : y0;
        float e1 = (2 * l + 1 < 32) ? x1 : y1;
        if (l < 21) {
            if (l == 20) e1 = 0.f;  // channel 41 pad
            ((__half2*)(h2h + node * H2S))[l] = __floats2half2_rn(e0, e1);
        }
    }
}

// ---------------- agg2: warp per dst, cp.async smem-staged (96B rows) --------
__global__ __launch_bounds__(256, 6) void agg2_kernel(const float* __restrict__ b2,
                                                      float* __restrict__ out) {
    __shared__ __align__(16) unsigned char buf[8][32 * 96];
    int wid = threadIdx.x >> 5;
    int w = blockIdx.x * 8 + wid;
    if (w >= NN) return;
    int l = threadIdx.x & 31;
    int dst = w;
    int li = l < 24 ? l : 23;
    unsigned bufw = (unsigned)__cvta_generic_to_shared(&buf[wid][0]);
    float dv = __ldg(d2g + dst);

    float ws = __expf(lrelu(__ldg(s2g + dst) + dv));
    unsigned hv = __ldg((const unsigned*)h2h + dst * 32 + li);
    float2 f = __half22float2(*(__half2*)&hv);
    float a0 = ws * f.x, a1 = ws * f.y, z = ws;

    // copy-role mapping: 24 active lanes; lane l -> edge-subgroup l/6, segment l%6
    int egrp6 = l / 6, seg6 = l - egrp6 * 6;
    bool cp_on = (l < 24);

    int beg = __ldg(offg + dst), end = __ldg(offg + dst + 1);
    for (int k0 = beg; k0 < end; k0 += 32) {
        int n = end - k0; if (n > 32) n = 32;
        int srcl = __ldg(csrg + k0 + (l < n ? l : n - 1));

#pragma unroll
        for (int st = 0; st < 8; st++) {
            int i = st * 4 + egrp6;
            int ii = i < n ? i : n - 1;
            int src = __shfl_sync(0xffffffffu, srcl, ii < 32 ? ii : 31);
            if (cp_on)
                CPA16(bufw + i * 96 + seg6 * 16,
                      (const char*)(h2h + src * 64) + seg6 * 16);
        }
        CPA_COMMIT();

        float wall = __expf(lrelu(__ldg(s2g + srcl) + dv));   // weight for edge l

        CPA_WAIT0();
        __syncwarp();
        for (int i = 0; i < n; i++) {
            float we = __shfl_sync(0xffffffffu, wall, i);
            unsigned hword = *(const unsigned*)&buf[wid][i * 96 + li * 4];
            float2 g = __half22float2(*(__half2*)&hword);
            a0 += we * g.x; a1 += we * g.y; z += we;
        }
        __syncwarp();   // buf reuse (WAR)
    }
    float inv = 1.0f / (z + 1e-16f);
    int c0 = 2 * l, c1 = 2 * l + 1;
    float v0 = (c0 < NCL) ? a0 * inv + __ldg(b2 + c0) : -1e30f;
    float v1 = (c1 < NCL) ? a1 * inv + __ldg(b2 + c1) : -1e30f;
    float m = fmaxf(v0, v1);
#pragma unroll
    for (int o = 16; o; o >>= 1) m = fmaxf(m, __shfl_xor_sync(0xffffffffu, m, o));
    float se = ((c0 < NCL) ? __expf(v0 - m) : 0.f) + ((c1 < NCL) ? __expf(v1 - m) : 0.f);
#pragma unroll
    for (int o = 16; o; o >>= 1) se += __shfl_xor_sync(0xffffffffu, se, o);
    float ls = m + logf(se);
    if (c0 < NCL) out[dst * NCL + c0] = v0 - ls;
    if (c1 < NCL) out[dst * NCL + c1] = v1 - ls;
}

// ---------------- launch ------------------------------------------------------
extern "C" void kernel_launch(void* const* d_in, const int* in_sizes, int n_in,
                              void* d_out, int out_size) {
    const float* x      = (const float*)d_in[0];
    const int*   ei     = (const int*)d_in[1];
    const float* W1     = (const float*)d_in[2];
    const float* a_src1 = (const float*)d_in[3];
    const float* a_dst1 = (const float*)d_in[4];
    const float* b1     = (const float*)d_in[5];
    const float* W2     = (const float*)d_in[6];
    const float* a_src2 = (const float*)d_in[7];
    const float* a_dst2 = (const float*)d_in[8];
    const float* b2     = (const float*)d_in[9];
    float*       out    = (float*)d_out;

    static cudaStream_t s2 = nullptr;
    static cudaEvent_t  evA = nullptr, evB = nullptr;
    static void* cnt_ptr = nullptr;
    if (!s2) {
        cudaStreamCreateWithFlags(&s2, cudaStreamNonBlocking);
        cudaEventCreateWithFlags(&evA, cudaEventDisableTiming);
        cudaEventCreateWithFlags(&evB, cudaEventDisableTiming);
        cudaGetSymbolAddress(&cnt_ptr, cntg);
    }

    // fork: GEMM1 chain on s2, CSR chain on main stream
    cudaEventRecord(evA, 0);
    cudaStreamWaitEvent(s2, evA, 0);
    prep_kernel<<<1, 256, 0, s2>>>(W1, a_src1, a_dst1);
    gemm1_tc<<<(NN + 127) / 128, 256, 0, s2>>>(x);
    cudaEventRecord(evB, s2);

    cudaMemsetAsync(cnt_ptr, 0, NN * sizeof(int), 0);
    hist_kernel<<<NE / 4 / 256, 256>>>(ei);
    scan1_kernel<<<(NN + 1023) / 1024, 1024>>>();
    scan2_kernel<<<1, 128>>>();
    scan3_kernel<<<(NN + 1023) / 1024, 1024>>>();
    scatter_kernel<<<NE / 4 / 256, 256>>>(ei);

    cudaStreamWaitEvent(0, evB, 0);   // join
    agg1_kernel<<<(NN + 7) / 8, 256>>>(b1);
    gemm2_kernel<<<(NN + 31) / 32, 256>>>(W2, a_src2, a_dst2);
    agg2_kernel<<<(NN + 7) / 8, 256>>>(b2, out);
}